// round 2
// baseline (speedup 1.0000x reference)
#include <cuda_runtime.h>

#define NFSZ 1001
#define HSZ   256
#define BSZ   64
#define FD    128
#define INCH  16
#define G4    1024   // 4*H
#define INS0  144    // FD + INCH

// scratch (device globals: allocation-free rule)
__device__ float g_Wt[FD * G4];     // transposed f-part of W_ih0: [k][g]
__device__ float g_Gf[NFSZ * G4];   // pre-scaled f-side gate pre-activations

__device__ __forceinline__ float ex2f(float x) {
    float y; asm("ex2.approx.f32 %0, %1;" : "=f"(y) : "f"(x)); return y;
}
__device__ __forceinline__ float rcpf(float x) {
    float y; asm("rcp.approx.f32 %0, %1;" : "=f"(y) : "f"(x)); return y;
}

// ---------------- precompute kernels ----------------

__global__ void transpose_kernel(const float* __restrict__ Wih0) {
    int idx = blockIdx.x * blockDim.x + threadIdx.x;   // 131072 total
    if (idx >= FD * G4) return;
    int g = idx / FD;          // consecutive idx -> consecutive k: coalesced reads
    int k = idx - g * FD;
    g_Wt[k * G4 + g] = Wih0[g * INS0 + k];
}

// Gf[t][g] = scale(g) * sum_k f[t,k] * Wih0[g,k],  scale folds -log2e (-2log2e for g-gate)
__global__ void gf_kernel(const float* __restrict__ f) {
    __shared__ float fs[8][FD];
    int tx = threadIdx.x;                   // 256
    int g  = blockIdx.y * 256 + tx;
    int t0 = blockIdx.x * 8;
    #pragma unroll
    for (int i = 0; i < 4; i++) {
        int e  = tx + i * 256;
        int tt = e >> 7, kk = e & 127;
        int t  = t0 + tt;
        fs[tt][kk] = (t < NFSZ) ? f[t * FD + kk] : 0.f;
    }
    __syncthreads();
    float acc[8] = {0.f,0.f,0.f,0.f,0.f,0.f,0.f,0.f};
    #pragma unroll 4
    for (int k = 0; k < FD; k++) {
        float w = g_Wt[k * G4 + g];
        #pragma unroll
        for (int tt = 0; tt < 8; tt++) acc[tt] = fmaf(fs[tt][k], w, acc[tt]);
    }
    float scale = ((g >> 8) == 2) ? -2.8853900817779268f : -1.4426950408889634f;
    #pragma unroll
    for (int tt = 0; tt < 8; tt++) {
        int t = t0 + tt;
        if (t < NFSZ) g_Gf[t * G4 + g] = acc[tt] * scale;
    }
}

// ---------------- main systolic LSTM kernel ----------------
// One CTA per batch element. 3 warpgroups (128 thr each) = 3 layers, pipelined:
// at tick k, layer l computes timestep t = k - l. Scalars (projected h) flow via
// parity-double-buffered smem partials; one __syncthreads per tick.

__global__ __launch_bounds__(384, 1) void lstm_kernel(
    const float* __restrict__ x,
    const float* __restrict__ Wih0, const float* __restrict__ Whh0,
    const float* __restrict__ bih0, const float* __restrict__ bhh0,
    const float* __restrict__ Whr0,
    const float* __restrict__ Wih1, const float* __restrict__ Whh1,
    const float* __restrict__ bih1, const float* __restrict__ bhh1,
    const float* __restrict__ Whr1,
    const float* __restrict__ Wih2, const float* __restrict__ Whh2,
    const float* __restrict__ bih2, const float* __restrict__ bhh2,
    const float* __restrict__ Whr2,
    float* __restrict__ out)
{
    __shared__ float part[2][3][16];   // [parity][layer][16 partials]

    const int b    = blockIdx.x;
    const int tid  = threadIdx.x;
    const int wg   = tid >> 7;         // layer id 0..2
    const int wtid = tid & 127;
    const int warp = wtid >> 5;
    const int lane = wtid & 31;
    const int u0   = wtid * 2;         // this thread owns hidden units u0, u0+1

    const float L2E  = 1.4426950408889634f;
    const float NL2E2 = -2.8853900817779268f;

    const float* Whh = (wg == 0) ? Whh0 : (wg == 1) ? Whh1 : Whh2;
    const float* Wih = (wg == 1) ? Wih1 : Wih2;
    const float* bih = (wg == 0) ? bih0 : (wg == 1) ? bih1 : bih2;
    const float* bhh = (wg == 0) ? bhh0 : (wg == 1) ? bhh1 : bhh2;
    const float* Whr = (wg == 0) ? Whr0 : (wg == 1) ? Whr1 : Whr2;

    // j = gate*2 + m : gate 0=i,1=f,2=g,3=o ; m = unit within thread
    float whh_s[8], base_s[8], wih_s[8];
    #pragma unroll
    for (int j = 0; j < 8; j++) {
        int gate = j >> 1;
        int idx  = gate * HSZ + u0 + (j & 1);
        float sc = (gate == 2) ? NL2E2 : -L2E;
        whh_s[j] = Whh[idx] * sc;
        float bias = bih[idx] + bhh[idx];
        if (wg == 0) {
            float acc = bias;   // fold x-side input (batch-constant) + bias
            #pragma unroll
            for (int kk = 0; kk < INCH; kk++)
                acc = fmaf(x[b * INCH + kk], Wih0[idx * INS0 + FD + kk], acc);
            base_s[j] = acc * sc;
            wih_s[j]  = 0.f;
        } else {
            base_s[j] = bias * sc;
            wih_s[j]  = Wih[idx] * sc;
        }
    }
    const float whr0v = Whr[u0];
    const float whr1v = Whr[u0 + 1];
    float c0 = 0.f, c1 = 0.f;

    if (wtid < 16) { part[0][wg][wtid] = 0.f; part[1][wg][wtid] = 0.f; }
    __syncthreads();

    // prefetch Gf row for t=0 (layer 0 only)
    float gfc[8];
    if (wg == 0) {
        #pragma unroll
        for (int gate = 0; gate < 4; gate++) {
            float2 v = *(const float2*)&g_Gf[gate * HSZ + u0];
            gfc[2 * gate] = v.x; gfc[2 * gate + 1] = v.y;
        }
    }

    for (int k = 0; k < NFSZ + 3; k++) {
        const int par = k & 1, rp = par ^ 1;
        const int t = k - wg;
        const bool active = (t >= 0) && (t < NFSZ);

        // early prefetch of next Gf row (hidden behind this tick's work)
        float gfn[8] = {0.f,0.f,0.f,0.f,0.f,0.f,0.f,0.f};
        if (wg == 0 && (t + 1) < NFSZ) {
            #pragma unroll
            for (int gate = 0; gate < 4; gate++) {
                float2 v = *(const float2*)&g_Gf[(t + 1) * G4 + gate * HSZ + u0];
                gfn[2 * gate] = v.x; gfn[2 * gate + 1] = v.y;
            }
        }

        // gather scalars produced last tick (16 partials each, broadcast LDS.128)
        float h_prev;
        {
            const float4* p = (const float4*)part[rp][wg];
            float4 a = p[0], q = p[1], r = p[2], d = p[3];
            h_prev = (((a.x + a.y) + (a.z + a.w)) + ((q.x + q.y) + (q.z + q.w)))
                   + (((r.x + r.y) + (r.z + r.w)) + ((d.x + d.y) + (d.z + d.w)));
        }
        float u_in = 0.f;
        if (wg > 0) {
            const float4* p = (const float4*)part[rp][wg - 1];
            float4 a = p[0], q = p[1], r = p[2], d = p[3];
            u_in = (((a.x + a.y) + (a.z + a.w)) + ((q.x + q.y) + (q.z + q.w)))
                 + (((r.x + r.y) + (r.z + r.w)) + ((d.x + d.y) + (d.z + d.w)));
        }
        if (wg == 2 && wtid == 0) {
            int to = k - 3;                     // layer-2 output for t = k-3
            if (to >= 0) out[b * NFSZ + to] = h_prev;
        }

        if (active) {
            float pre[8];
            #pragma unroll
            for (int j = 0; j < 8; j++) {
                float gx = (wg == 0) ? (base_s[j] + gfc[j])
                                     : fmaf(wih_s[j], u_in, base_s[j]);
                pre[j] = fmaf(whh_s[j], h_prev, gx);   // pre-scaled by -log2e / -2log2e
            }
            float partial = 0.f;
            #pragma unroll
            for (int m = 0; m < 2; m++) {
                float ei = ex2f(pre[m]);            // e^{-i}
                float ef = ex2f(pre[2 + m]);        // e^{-f}
                float gs = pre[4 + m];              // -2*log2e*g
                float eg = ex2f(-fabsf(gs));        // e^{-2|g|}
                float eo = ex2f(pre[6 + m]);        // e^{-o}
                float sf = rcpf(1.f + ef);                               // sigmoid(f)
                float mag = (1.f - eg) * rcpf((1.f + ei) * (1.f + eg));  // sig(i)*tanh|g|
                float itg = copysignf(mag, -gs);
                float c = (m == 0) ? c0 : c1;
                c = fmaf(sf, c, itg);
                float ec = ex2f(NL2E2 * fabsf(c));                       // e^{-2|c|}
                float hm = (1.f - ec) * rcpf((1.f + eo) * (1.f + ec));   // sig(o)*tanh|c|
                float hr = copysignf(hm, c);
                if (m == 0) { c0 = c; partial = fmaf(hr, whr0v, partial); }
                else        { c1 = c; partial = fmaf(hr, whr1v, partial); }
            }
            // 3-level butterfly -> 4 partials per warp (shorter chain than full 5-level)
            partial += __shfl_xor_sync(0xffffffffu, partial, 16);
            partial += __shfl_xor_sync(0xffffffffu, partial, 8);
            partial += __shfl_xor_sync(0xffffffffu, partial, 4);
            if (lane < 4) part[par][wg][warp * 4 + lane] = partial;
        }
        if (wg == 0) {
            #pragma unroll
            for (int j = 0; j < 8; j++) gfc[j] = gfn[j];
        }
        __syncthreads();
    }
}

// ---------------- launch ----------------

extern "C" void kernel_launch(void* const* d_in, const int* in_sizes, int n_in,
                              void* d_out, int out_size) {
    const float* x    = (const float*)d_in[0];
    const float* f    = (const float*)d_in[1];
    const float* Wih0 = (const float*)d_in[2];
    const float* Whh0 = (const float*)d_in[3];
    const float* bih0 = (const float*)d_in[4];
    const float* bhh0 = (const float*)d_in[5];
    const float* Whr0 = (const float*)d_in[6];
    const float* Wih1 = (const float*)d_in[7];
    const float* Whh1 = (const float*)d_in[8];
    const float* bih1 = (const float*)d_in[9];
    const float* bhh1 = (const float*)d_in[10];
    const float* Whr1 = (const float*)d_in[11];
    const float* Wih2 = (const float*)d_in[12];
    const float* Whh2 = (const float*)d_in[13];
    const float* bih2 = (const float*)d_in[14];
    const float* bhh2 = (const float*)d_in[15];
    const float* Whr2 = (const float*)d_in[16];

    transpose_kernel<<<512, 256>>>(Wih0);
    gf_kernel<<<dim3(126, 4), 256>>>(f);
    lstm_kernel<<<BSZ, 384>>>(x,
                              Wih0, Whh0, bih0, bhh0, Whr0,
                              Wih1, Whh1, bih1, bhh1, Whr1,
                              Wih2, Whh2, bih2, bhh2, Whr2,
                              (float*)d_out);
}